// round 2
// baseline (speedup 1.0000x reference)
#include <cuda_runtime.h>
#include <cstdint>

// Problem constants
#define NB   2048
#define NTT  1024
#define NF   10            // FEAT = 1 + 9
#define NROWS (NB * NTT)   // 2,097,152
#define TILE_ROWS 128
#define NTILES (NROWS / TILE_ROWS)  // 16384
#define GRID_PERSIST 148

// ---- shared memory layout (in floats) ----
#define OFF_W2 0
#define OFF_H1 (OFF_W2 + 128*128)           // reused as h2 buffer in epilogue
#define OFF_XS (OFF_H1 + 128*128)
#define OFF_W1 (OFF_XS + TILE_ROWS*NF)
#define OFF_B1 (OFF_W1 + 9*128)
#define OFF_B2 (OFF_B1 + 128)
#define OFF_W3 (OFF_B2 + 128)
#define SMEM_FLOATS (OFF_W3 + 256)
#define SMEM_BYTES  (SMEM_FLOATS * 4)       // 142,848 bytes

// Accurate-enough fast tanh: EX2 + RCP (MUFU pipe), abs err ~1e-6.
// Handles saturation: x->+inf => e=inf => 1 - 0 = 1; x->-inf => e=0 => -1.
__device__ __forceinline__ float fast_tanh(float x) {
    float e = __expf(2.0f * x);
    return 1.0f - __fdividef(2.0f, e + 1.0f);
}

// ============================================================================
// Kernel A: sequential RK4 scan of the 2-state linear ODE, one thread per
// batch row. Writes the PRE-update state xG_t into out[(b*T+t)*2 + {0,1}].
// Kernel B later does out += r (the MLP correction).
// ============================================================================
__global__ void scan_kernel(const float* __restrict__ inputs,
                            const float* __restrict__ x0,
                            float* __restrict__ out) {
    int b = blockIdx.x * blockDim.x + threadIdx.x;
    if (b >= NB) return;

    const float it  = 1.0f / 10.0f;   // 1/TAU
    const float dlt = 0.1f;           // DELTA
    float Ca = x0[2 * b];
    float Cb = x0[2 * b + 1];

    const float* up = inputs + (size_t)b * NTT * NF;
    float2* op = (float2*)(out + (size_t)b * NTT * 2);

    float u_next = up[0];
    for (int t = 0; t < NTT; ++t) {
        float u = u_next;
        if (t + 1 < NTT) u_next = up[(size_t)(t + 1) * NF];  // prefetch next u

        op[t] = make_float2(Ca, Cb);   // y uses pre-update state

        // RK4 exactly as the reference
        float k1a = (u - Ca) * it - Ca;
        float k1b = Ca - Cb * it;
        float xa  = Ca + 0.5f * dlt * k1a;
        float xb  = Cb + 0.5f * dlt * k1b;
        float k2a = (u - xa) * it - xa;
        float k2b = xa - xb * it;
        xa = Ca + 0.5f * dlt * k2a;
        xb = Cb + 0.5f * dlt * k2b;
        float k3a = (u - xa) * it - xa;
        float k3b = xa - xb * it;
        xa = Ca + dlt * k3a;
        xb = Cb + dlt * k3b;
        float k4a = (u - xa) * it - xa;
        float k4b = xa - xb * it;
        Ca += (dlt / 6.0f) * (k1a + 2.0f * k2a + 2.0f * k3a + k4a);
        Cb += (dlt / 6.0f) * (k1b + 2.0f * k2b + 2.0f * k3b + k4b);
    }
}

// ============================================================================
// Kernel B: persistent fused MLP.
//   h1 = tanh(seq @ W1 + b1)   (K=9, CUDA cores)
//   h2 = tanh(h1  @ W2 + b2)   (128x128x128 per tile, 8x8 register tiling)
//   r  = h2 @ W3               (N=2, smem-staged reduction)
//   out += r
// W1/W2/W3/b1/b2 loaded to smem ONCE per CTA (grid=148 persistent).
// ============================================================================
__global__ void __launch_bounds__(256, 1)
mlp_kernel(const float* __restrict__ inputs,
           const float* __restrict__ W1,
           const float* __restrict__ b1,
           const float* __restrict__ W2,
           const float* __restrict__ b2,
           const float* __restrict__ W3,
           float* __restrict__ out) {
    extern __shared__ float sm[];
    const int tid = threadIdx.x;

    // ---- one-time weight staging ----
    {
        const float4* g2 = (const float4*)W2;
        float4* s2 = (float4*)(sm + OFF_W2);
        #pragma unroll
        for (int i = 0; i < 16; ++i) s2[tid + 256 * i] = g2[tid + 256 * i];  // 4096 float4

        // W1 is 9*128 floats = 288 float4 > 256 threads: grid-stride it.
        const float4* g1 = (const float4*)W1;
        float4* s1 = (float4*)(sm + OFF_W1);
        for (int i = tid; i < 288; i += 256) s1[i] = g1[i];

        if (tid < 32)  ((float4*)(sm + OFF_B1))[tid] = ((const float4*)b1)[tid];
        else if (tid < 64)  ((float4*)(sm + OFF_B2))[tid - 32] = ((const float4*)b2)[tid - 32];
        else if (tid < 128) ((float4*)(sm + OFF_W3))[tid - 64] = ((const float4*)W3)[tid - 64];
    }

    const int row = tid & 127;     // GEMM1 row
    const int jh  = tid >> 7;      // GEMM1 j half (0/1)
    const int ty  = tid >> 4;      // GEMM2 row group (0..15) -> rows ty*8..+7
    const int tx  = tid & 15;      // GEMM2 col group (0..15) -> cols tx*8..+7
    const int rrow = tid >> 1;     // reduce row
    const int half = tid & 1;      // reduce col half

    for (int tile = blockIdx.x; tile < NTILES; tile += GRID_PERSIST) {
        __syncthreads();  // prev tile fully done (h1 buffer free, xs free);
                          // also fences the one-time weight staging.

        // ---- stage X tile (coalesced) ----
        {
            const float* gx = inputs + (size_t)tile * TILE_ROWS * NF;
            #pragma unroll
            for (int i = 0; i < 5; ++i) sm[OFF_XS + tid + 256 * i] = gx[tid + 256 * i];
        }
        __syncthreads();

        // ---- GEMM1: h1T[j][row] = tanh(seq . W1[:,j] + b1[j]) ----
        {
            float x[9];
            #pragma unroll
            for (int k = 0; k < 9; ++k) x[k] = sm[OFF_XS + row * NF + 1 + k];
            const float4* W1v = (const float4*)(sm + OFF_W1);
            const float4* b1v = (const float4*)(sm + OFF_B1);
            const int j4base = jh * 16;
            #pragma unroll
            for (int q = 0; q < 16; ++q) {
                const int j4 = j4base + q;
                float4 a = b1v[j4];
                #pragma unroll
                for (int k = 0; k < 9; ++k) {
                    float4 w = W1v[k * 32 + j4];
                    a.x = fmaf(x[k], w.x, a.x);
                    a.y = fmaf(x[k], w.y, a.y);
                    a.z = fmaf(x[k], w.z, a.z);
                    a.w = fmaf(x[k], w.w, a.w);
                }
                const int j = j4 * 4;
                sm[OFF_H1 + (j + 0) * 128 + row] = fast_tanh(a.x);
                sm[OFF_H1 + (j + 1) * 128 + row] = fast_tanh(a.y);
                sm[OFF_H1 + (j + 2) * 128 + row] = fast_tanh(a.z);
                sm[OFF_H1 + (j + 3) * 128 + row] = fast_tanh(a.w);
            }
        }
        __syncthreads();

        // ---- GEMM2: 128x128x128, 8x8 per-thread register tile ----
        float acc[8][8];
        #pragma unroll
        for (int i = 0; i < 8; ++i)
            #pragma unroll
            for (int j = 0; j < 8; ++j) acc[i][j] = 0.0f;

        {
            const float4* hv = (const float4*)(sm + OFF_H1);
            const float4* wv = (const float4*)(sm + OFF_W2);
            #pragma unroll 4
            for (int k = 0; k < 128; ++k) {
                float4 h0 = hv[k * 32 + ty * 2];
                float4 h1 = hv[k * 32 + ty * 2 + 1];
                float4 w0 = wv[k * 32 + tx * 2];
                float4 w1 = wv[k * 32 + tx * 2 + 1];
                float hr[8] = {h0.x, h0.y, h0.z, h0.w, h1.x, h1.y, h1.z, h1.w};
                float wr[8] = {w0.x, w0.y, w0.z, w0.w, w1.x, w1.y, w1.z, w1.w};
                #pragma unroll
                for (int i = 0; i < 8; ++i)
                    #pragma unroll
                    for (int j = 0; j < 8; ++j)
                        acc[i][j] = fmaf(hr[i], wr[j], acc[i][j]);
            }
        }
        __syncthreads();  // all h1 reads done; reuse buffer for h2

        // ---- epilogue: h2 = tanh(acc + b2) staged to smem ----
        {
            float* h2s = sm + OFF_H1;
            float bb[8];
            #pragma unroll
            for (int j = 0; j < 8; ++j) bb[j] = sm[OFF_B2 + tx * 8 + j];
            #pragma unroll
            for (int i = 0; i < 8; ++i) {
                const int r = ty * 8 + i;
                float4 v0, v1;
                v0.x = fast_tanh(acc[i][0] + bb[0]);
                v0.y = fast_tanh(acc[i][1] + bb[1]);
                v0.z = fast_tanh(acc[i][2] + bb[2]);
                v0.w = fast_tanh(acc[i][3] + bb[3]);
                v1.x = fast_tanh(acc[i][4] + bb[4]);
                v1.y = fast_tanh(acc[i][5] + bb[5]);
                v1.z = fast_tanh(acc[i][6] + bb[6]);
                v1.w = fast_tanh(acc[i][7] + bb[7]);
                *((float4*)(h2s + r * 128 + tx * 8))     = v0;
                *((float4*)(h2s + r * 128 + tx * 8 + 4)) = v1;
            }
        }
        __syncthreads();

        // ---- GEMM3 + add xG: r[row] = h2[row] . W3 ; out += r ----
        {
            const float* h2s = sm + OFF_H1;
            const float* W3s = sm + OFF_W3;
            const float4* hrv = (const float4*)(h2s + rrow * 128 + half * 64);
            float r0 = 0.0f, r1 = 0.0f;
            #pragma unroll
            for (int c4 = 0; c4 < 16; ++c4) {
                float4 h = hrv[c4];
                const int c = half * 64 + c4 * 4;
                r0 = fmaf(h.x, W3s[2 * c + 0], r0);
                r1 = fmaf(h.x, W3s[2 * c + 1], r1);
                r0 = fmaf(h.y, W3s[2 * c + 2], r0);
                r1 = fmaf(h.y, W3s[2 * c + 3], r1);
                r0 = fmaf(h.z, W3s[2 * c + 4], r0);
                r1 = fmaf(h.z, W3s[2 * c + 5], r1);
                r0 = fmaf(h.w, W3s[2 * c + 6], r0);
                r1 = fmaf(h.w, W3s[2 * c + 7], r1);
            }
            r0 += __shfl_xor_sync(0xffffffffu, r0, 1);
            r1 += __shfl_xor_sync(0xffffffffu, r1, 1);
            if (half == 0) {
                const size_t o = ((size_t)tile * TILE_ROWS + rrow) * 2;
                out[o]     += r0;   // out currently holds xG (kernel A)
                out[o + 1] += r1;
            }
        }
    }
}

// ============================================================================
extern "C" void kernel_launch(void* const* d_in, const int* in_sizes, int n_in,
                              void* d_out, int out_size) {
    const float* inputs = (const float*)d_in[0];
    const float* x0     = (const float*)d_in[1];
    const float* W1     = (const float*)d_in[2];
    const float* b1     = (const float*)d_in[3];
    const float* W2     = (const float*)d_in[4];
    const float* b2     = (const float*)d_in[5];
    const float* W3     = (const float*)d_in[6];
    float* out = (float*)d_out;

    // opt-in to >48KB dynamic smem (idempotent; not a stream op, capture-safe)
    cudaFuncSetAttribute(mlp_kernel,
                         cudaFuncAttributeMaxDynamicSharedMemorySize, SMEM_BYTES);

    scan_kernel<<<NB / 128, 128>>>(inputs, x0, out);
    mlp_kernel<<<GRID_PERSIST, 256, SMEM_BYTES>>>(inputs, W1, b1, W2, b2, W3, out);
}

// round 4
// speedup vs baseline: 1.6896x; 1.6896x over previous
#include <cuda_runtime.h>
#include <cuda_bf16.h>
#include <cstdint>

// ---------------- problem constants ----------------
#define NB   2048
#define NTT  1024
#define NF   10
#define NROWS (NB * NTT)
#define TILE_ROWS 128
#define NTILES (NROWS / TILE_ROWS)   // 16384
#define GRID_PERSIST 148
#define THREADS 256

// ---------------- smem layout (bytes) ----------------
// A/B matrices stored padded: 128 rows x 128 bf16, row stride 272B (17*16B)
// -> ldmatrix 16B row-chunks land on distinct banks for any 8 consecutive rows.
#define MAT_STRIDE 272
#define MAT_BYTES  (128 * MAT_STRIDE)   // 34816

#define OFF_XS   0                       // 1280 floats = 5120 B
#define OFF_W1   5120                    // 1152 floats = 4608 B
#define OFF_B1   9728                    // 128 floats (+pad)
#define OFF_B2   10240
#define OFF_W3   10752                   // 256 floats
#define OFF_RED  11776                   // 128 float2 = 1024 B
#define OFF_AHI  12800
#define OFF_ALO  (OFF_AHI + MAT_BYTES)   // 47616
#define OFF_BHI  (OFF_ALO + MAT_BYTES)   // 82432
#define OFF_BLO  (OFF_BHI + MAT_BYTES)   // 117248
#define SMEM_BYTES (OFF_BLO + MAT_BYTES) // 152064

// ---------------- PTX helpers ----------------
__device__ __forceinline__ uint32_t smem_u32(const void* p) {
    uint32_t a;
    asm("{ .reg .u64 t; cvta.to.shared.u64 t, %1; cvt.u32.u64 %0, t; }" : "=r"(a) : "l"(p));
    return a;
}
__device__ __forceinline__ void ldm_x4(uint32_t* r, uint32_t addr) {
    asm volatile("ldmatrix.sync.aligned.m8n8.x4.shared.b16 {%0,%1,%2,%3}, [%4];"
                 : "=r"(r[0]), "=r"(r[1]), "=r"(r[2]), "=r"(r[3]) : "r"(addr));
}
__device__ __forceinline__ void mma_bf16(float* d, const uint32_t* a, const uint32_t* b) {
    asm volatile(
        "mma.sync.aligned.m16n8k16.row.col.f32.bf16.bf16.f32 "
        "{%0,%1,%2,%3}, {%4,%5,%6,%7}, {%8,%9}, {%0,%1,%2,%3};"
        : "+f"(d[0]), "+f"(d[1]), "+f"(d[2]), "+f"(d[3])
        : "r"(a[0]), "r"(a[1]), "r"(a[2]), "r"(a[3]), "r"(b[0]), "r"(b[1]));
}

// ---------------- math helpers ----------------
__device__ __forceinline__ float fast_tanh(float x) {
    float e = __expf(2.0f * x);
    return 1.0f - __fdividef(2.0f, e + 1.0f);
}

// ============================================================================
// Kernel A (proven in R2): sequential RK4 scan, one thread per batch row.
// Writes the PRE-update state xG_t into out; MLP kernel later adds r.
// ============================================================================
__global__ void scan_kernel(const float* __restrict__ inputs,
                            const float* __restrict__ x0,
                            float* __restrict__ out) {
    int b = blockIdx.x * blockDim.x + threadIdx.x;
    if (b >= NB) return;

    const float it  = 0.1f;   // 1/TAU
    const float dlt = 0.1f;   // DELTA
    float Ca = x0[2 * b];
    float Cb = x0[2 * b + 1];

    const float* up = inputs + (size_t)b * NTT * NF;
    float2* op = (float2*)(out + (size_t)b * NTT * 2);

    float u_next = up[0];
    for (int t = 0; t < NTT; ++t) {
        float u = u_next;
        if (t + 1 < NTT) u_next = up[(size_t)(t + 1) * NF];

        op[t] = make_float2(Ca, Cb);

        float k1a = (u - Ca) * it - Ca;
        float k1b = Ca - Cb * it;
        float xa  = Ca + 0.5f * dlt * k1a;
        float xb  = Cb + 0.5f * dlt * k1b;
        float k2a = (u - xa) * it - xa;
        float k2b = xa - xb * it;
        xa = Ca + 0.5f * dlt * k2a;
        xb = Cb + 0.5f * dlt * k2b;
        float k3a = (u - xa) * it - xa;
        float k3b = xa - xb * it;
        xa = Ca + dlt * k3a;
        xb = Cb + dlt * k3b;
        float k4a = (u - xa) * it - xa;
        float k4b = xa - xb * it;
        Ca += (dlt / 6.0f) * (k1a + 2.0f * k2a + 2.0f * k3a + k4a);
        Cb += (dlt / 6.0f) * (k1b + 2.0f * k2b + 2.0f * k3b + k4b);
    }
}

// ============================================================================
// Kernel B: persistent fused MLP, GEMM2 on tensor cores via mma.sync bf16
// hi/lo split (3 passes: Ahi*Bhi + Ahi*Blo + Alo*Bhi), fp32 accumulators in
// registers, epilogue fully register-resident.
// Warp w: m-group mg=w&3 (rows 32*mg..+31), n-group ng=w>>2 (cols 64*ng..+63).
// ============================================================================
__global__ void __launch_bounds__(THREADS, 1)
mlp_kernel(const float* __restrict__ inputs,
           const float* __restrict__ W1,
           const float* __restrict__ b1,
           const float* __restrict__ W2,
           const float* __restrict__ b2,
           const float* __restrict__ W3,
           float* __restrict__ out) {
    extern __shared__ char smem[];
    const uint32_t smb = smem_u32(smem);
    const int tid  = threadIdx.x;
    const int wid  = tid >> 5;
    const int lane = tid & 31;

    // ---- one-time weight staging ----
    {
        // W2 (k-major [k][n]) -> Bsm[n][k] hi/lo bf16, padded stride.
        for (int i = tid; i < 16384; i += THREADS) {
            int k = i >> 7, n = i & 127;
            float w = W2[i];                         // coalesced read
            __nv_bfloat16 hb = __float2bfloat16(w);
            __nv_bfloat16 lb = __float2bfloat16(w - __bfloat162float(hb));
            uint32_t byte = (uint32_t)(n * MAT_STRIDE + k * 2);
            *(__nv_bfloat16*)(smem + OFF_BHI + byte) = hb;
            *(__nv_bfloat16*)(smem + OFF_BLO + byte) = lb;
        }
        float4* s1 = (float4*)(smem + OFF_W1);
        const float4* g1 = (const float4*)W1;
        for (int i = tid; i < 288; i += THREADS) s1[i] = g1[i];
        if (tid < 32)       ((float4*)(smem + OFF_B1))[tid]       = ((const float4*)b1)[tid];
        else if (tid < 64)  ((float4*)(smem + OFF_B2))[tid - 32]  = ((const float4*)b2)[tid - 32];
        else if (tid < 128) ((float4*)(smem + OFF_W3))[tid - 64]  = ((const float4*)W3)[tid - 64];
    }

    const int row = tid & 127;     // GEMM1 row
    const int jh  = tid >> 7;      // GEMM1 col half (64 cols each)
    const int mg  = wid & 3;       // MMA m-group
    const int ng  = wid >> 2;      // MMA n-group
    const int R0  = mg * 32;
    const int N0  = ng * 64;

    float*  xs  = (float*)(smem + OFF_XS);
    float*  b2s = (float*)(smem + OFF_B2);
    float*  W3s = (float*)(smem + OFF_W3);
    float2* red = (float2*)(smem + OFF_RED);
    const float4* W1v = (const float4*)(smem + OFF_W1);
    const float4* b1v = (const float4*)(smem + OFF_B1);

    // per-thread ldmatrix address components (constant across tiles)
    const int a_row = ((lane >> 3) & 1) * 8 + (lane & 7);   // + k-half via lane>>4
    const int a_kh  = ((lane >> 4) & 1) * 16;
    const int b_row = ((lane >> 4) & 1) * 8 + (lane & 7);
    const int b_kh  = ((lane >> 3) & 1) * 16;

    for (int tile = blockIdx.x; tile < NTILES; tile += GRID_PERSIST) {
        __syncthreads();   // prior tile retired; weight staging fenced on 1st iter

        // ---- stage X tile ----
        {
            const float* gx = inputs + (size_t)tile * TILE_ROWS * NF;
            #pragma unroll
            for (int i = 0; i < 5; ++i) xs[tid + THREADS * i] = gx[tid + THREADS * i];
        }
        __syncthreads();

        // ---- GEMM1 + tanh + hi/lo split into padded A tiles ----
        {
            float x[9];
            #pragma unroll
            for (int k = 0; k < 9; ++k) x[k] = xs[row * NF + 1 + k];
            #pragma unroll
            for (int q = 0; q < 16; ++q) {
                const int j4 = jh * 16 + q;
                float4 a = b1v[j4];
                #pragma unroll
                for (int k = 0; k < 9; ++k) {
                    float4 w = W1v[k * 32 + j4];
                    a.x = fmaf(x[k], w.x, a.x);
                    a.y = fmaf(x[k], w.y, a.y);
                    a.z = fmaf(x[k], w.z, a.z);
                    a.w = fmaf(x[k], w.w, a.w);
                }
                float t0 = fast_tanh(a.x), t1 = fast_tanh(a.y);
                float t2 = fast_tanh(a.z), t3 = fast_tanh(a.w);
                __nv_bfloat16 h0 = __float2bfloat16(t0), h1 = __float2bfloat16(t1);
                __nv_bfloat16 h2 = __float2bfloat16(t2), h3 = __float2bfloat16(t3);
                __nv_bfloat16 l0 = __float2bfloat16(t0 - __bfloat162float(h0));
                __nv_bfloat16 l1 = __float2bfloat16(t1 - __bfloat162float(h1));
                __nv_bfloat16 l2 = __float2bfloat16(t2 - __bfloat162float(h2));
                __nv_bfloat16 l3 = __float2bfloat16(t3 - __bfloat162float(h3));
                uint2 hv, lv;
                hv.x = (uint32_t)__bfloat16_as_ushort(h0) | ((uint32_t)__bfloat16_as_ushort(h1) << 16);
                hv.y = (uint32_t)__bfloat16_as_ushort(h2) | ((uint32_t)__bfloat16_as_ushort(h3) << 16);
                lv.x = (uint32_t)__bfloat16_as_ushort(l0) | ((uint32_t)__bfloat16_as_ushort(l1) << 16);
                lv.y = (uint32_t)__bfloat16_as_ushort(l2) | ((uint32_t)__bfloat16_as_ushort(l3) << 16);
                const uint32_t byte = (uint32_t)(row * MAT_STRIDE + jh * 128 + q * 8);
                *(uint2*)(smem + OFF_AHI + byte) = hv;
                *(uint2*)(smem + OFF_ALO + byte) = lv;
            }
        }
        __syncthreads();

        // ---- GEMM2: mma.sync bf16 3-pass ----
        float acc[2][8][4];
        #pragma unroll
        for (int mt = 0; mt < 2; ++mt)
            #pragma unroll
            for (int nt = 0; nt < 8; ++nt)
                #pragma unroll
                for (int c = 0; c < 4; ++c) acc[mt][nt][c] = 0.0f;

        #pragma unroll
        for (int ks = 0; ks < 8; ++ks) {
            const int K0 = ks * 32;   // byte offset of this k16 step
            uint32_t ahi[2][4], alo[2][4], bhi[8][2], blo[8][2];
            #pragma unroll
            for (int mt = 0; mt < 2; ++mt) {
                uint32_t addr = smb + (uint32_t)((R0 + mt * 16 + a_row) * MAT_STRIDE + K0 + a_kh);
                ldm_x4(ahi[mt], addr + OFF_AHI);
                ldm_x4(alo[mt], addr + OFF_ALO);
            }
            #pragma unroll
            for (int np = 0; np < 4; ++np) {
                uint32_t addr = smb + (uint32_t)((N0 + np * 16 + b_row) * MAT_STRIDE + K0 + b_kh);
                uint32_t r4[4];
                ldm_x4(r4, addr + OFF_BHI);
                bhi[2 * np][0] = r4[0]; bhi[2 * np][1] = r4[1];
                bhi[2 * np + 1][0] = r4[2]; bhi[2 * np + 1][1] = r4[3];
                ldm_x4(r4, addr + OFF_BLO);
                blo[2 * np][0] = r4[0]; blo[2 * np][1] = r4[1];
                blo[2 * np + 1][0] = r4[2]; blo[2 * np + 1][1] = r4[3];
            }
            #pragma unroll
            for (int mt = 0; mt < 2; ++mt)
                #pragma unroll
                for (int nt = 0; nt < 8; ++nt) {
                    mma_bf16(acc[mt][nt], ahi[mt], bhi[nt]);
                    mma_bf16(acc[mt][nt], ahi[mt], blo[nt]);
                    mma_bf16(acc[mt][nt], alo[mt], bhi[nt]);
                }
        }

        // ---- epilogue: tanh(acc + b2) @ W3, registers + quad shfl ----
        // thread holds rows: R0 + mt*16 + (lane>>2) + half*8 ; cols: N0 + nt*8 + 2*(lane&3)+{0,1}
        float rr[2][2][2];   // [mt][half][out component]
        #pragma unroll
        for (int mt = 0; mt < 2; ++mt)
            #pragma unroll
            for (int hf = 0; hf < 2; ++hf) { rr[mt][hf][0] = 0.f; rr[mt][hf][1] = 0.f; }

        #pragma unroll
        for (int mt = 0; mt < 2; ++mt)
            #pragma unroll
            for (int nt = 0; nt < 8; ++nt) {
                const int c0 = N0 + nt * 8 + 2 * (lane & 3);
                const float w300 = W3s[2 * c0],     w301 = W3s[2 * c0 + 1];
                const float w310 = W3s[2 * c0 + 2], w311 = W3s[2 * c0 + 3];
                const float bb0 = b2s[c0], bb1 = b2s[c0 + 1];
                float h;
                h = fast_tanh(acc[mt][nt][0] + bb0);
                rr[mt][0][0] = fmaf(h, w300, rr[mt][0][0]);
                rr[mt][0][1] = fmaf(h, w301, rr[mt][0][1]);
                h = fast_tanh(acc[mt][nt][1] + bb1);
                rr[mt][0][0] = fmaf(h, w310, rr[mt][0][0]);
                rr[mt][0][1] = fmaf(h, w311, rr[mt][0][1]);
                h = fast_tanh(acc[mt][nt][2] + bb0);
                rr[mt][1][0] = fmaf(h, w300, rr[mt][1][0]);
                rr[mt][1][1] = fmaf(h, w301, rr[mt][1][1]);
                h = fast_tanh(acc[mt][nt][3] + bb1);
                rr[mt][1][0] = fmaf(h, w310, rr[mt][1][0]);
                rr[mt][1][1] = fmaf(h, w311, rr[mt][1][1]);
            }
        // reduce across quad (lanes sharing lane>>2)
        #pragma unroll
        for (int mt = 0; mt < 2; ++mt)
            #pragma unroll
            for (int hf = 0; hf < 2; ++hf)
                #pragma unroll
                for (int c = 0; c < 2; ++c) {
                    float v = rr[mt][hf][c];
                    v += __shfl_xor_sync(0xffffffffu, v, 1);
                    v += __shfl_xor_sync(0xffffffffu, v, 2);
                    rr[mt][hf][c] = v;
                }

        if (ng == 1 && (lane & 3) == 0) {
            #pragma unroll
            for (int mt = 0; mt < 2; ++mt)
                #pragma unroll
                for (int hf = 0; hf < 2; ++hf) {
                    const int r = R0 + mt * 16 + hf * 8 + (lane >> 2);
                    red[r] = make_float2(rr[mt][hf][0], rr[mt][hf][1]);
                }
        }
        __syncthreads();
        if (ng == 0 && (lane & 3) == 0) {
            #pragma unroll
            for (int mt = 0; mt < 2; ++mt)
                #pragma unroll
                for (int hf = 0; hf < 2; ++hf) {
                    const int r = R0 + mt * 16 + hf * 8 + (lane >> 2);
                    const float2 p = red[r];
                    const size_t o = ((size_t)tile * TILE_ROWS + r) * 2;
                    float2 v = *(float2*)(out + o);       // xG from scan
                    v.x += rr[mt][hf][0] + p.x;
                    v.y += rr[mt][hf][1] + p.y;
                    *(float2*)(out + o) = v;
                }
        }
    }
}

// ============================================================================
extern "C" void kernel_launch(void* const* d_in, const int* in_sizes, int n_in,
                              void* d_out, int out_size) {
    const float* inputs = (const float*)d_in[0];
    const float* x0     = (const float*)d_in[1];
    const float* W1     = (const float*)d_in[2];
    const float* b1     = (const float*)d_in[3];
    const float* W2     = (const float*)d_in[4];
    const float* b2     = (const float*)d_in[5];
    const float* W3     = (const float*)d_in[6];
    float* out = (float*)d_out;

    cudaFuncSetAttribute(mlp_kernel,
                         cudaFuncAttributeMaxDynamicSharedMemorySize, SMEM_BYTES);

    scan_kernel<<<NB / 128, 128>>>(inputs, x0, out);
    mlp_kernel<<<GRID_PERSIST, THREADS, SMEM_BYTES>>>(inputs, W1, b1, W2, b2, W3, out);
}

// round 6
// speedup vs baseline: 2.1264x; 1.2585x over previous
#include <cuda_runtime.h>
#include <cuda_bf16.h>
#include <cstdint>

// ---------------- problem constants ----------------
#define NB   2048
#define NTT  1024
#define NF   10
#define NROWS (NB * NTT)
#define TILE_ROWS 128
#define NTILES (NROWS / TILE_ROWS)   // 16384
#define GRID_PERSIST 148
#define THREADS 512

// scan chunking
#define CHUNK 64
#define NCH (NTT / CHUNK)            // 16

// ---------------- smem layout (bytes) ----------------
#define MAT_STRIDE 272               // 128 bf16 cols padded to 17*16B
#define MAT_BYTES  (128 * MAT_STRIDE)

#define OFF_XS   0                       // 1280 floats = 5120 B
#define OFF_W1   5120                    // 1152 floats = 4608 B
#define OFF_B1   9728
#define OFF_B2   10240
#define OFF_W3   10752                   // 256 floats = 1024 B
#define OFF_RED  11776                   // 4 ngroups x 128 x float2 = 4096 B
#define OFF_AHI  15872
#define OFF_ALO  (OFF_AHI + MAT_BYTES)
#define OFF_BHI  (OFF_ALO + MAT_BYTES)
#define OFF_BLO  (OFF_BHI + MAT_BYTES)
#define SMEM_BYTES (OFF_BLO + MAT_BYTES) // 155136

// ---------------- PTX helpers ----------------
__device__ __forceinline__ uint32_t smem_u32(const void* p) {
    uint32_t a;
    asm("{ .reg .u64 t; cvta.to.shared.u64 t, %1; cvt.u32.u64 %0, t; }" : "=r"(a) : "l"(p));
    return a;
}
__device__ __forceinline__ void ldm_x4(uint32_t* r, uint32_t addr) {
    asm volatile("ldmatrix.sync.aligned.m8n8.x4.shared.b16 {%0,%1,%2,%3}, [%4];"
                 : "=r"(r[0]), "=r"(r[1]), "=r"(r[2]), "=r"(r[3]) : "r"(addr));
}
__device__ __forceinline__ void mma_bf16(float* d, const uint32_t* a, const uint32_t* b) {
    asm volatile(
        "mma.sync.aligned.m16n8k16.row.col.f32.bf16.bf16.f32 "
        "{%0,%1,%2,%3}, {%4,%5,%6,%7}, {%8,%9}, {%0,%1,%2,%3};"
        : "+f"(d[0]), "+f"(d[1]), "+f"(d[2]), "+f"(d[3])
        : "r"(a[0]), "r"(a[1]), "r"(a[2]), "r"(a[3]), "r"(b[0]), "r"(b[1]));
}

// ---------------- math helpers ----------------
__device__ __forceinline__ float fast_tanh(float x) {
    float e = __expf(2.0f * x);
    return 1.0f - __fdividef(2.0f, e + 1.0f);
}
// exact RK4 step, same arithmetic as reference
__device__ __forceinline__ void rk4_step(float& Ca, float& Cb, float u) {
    const float it = 0.1f, dlt = 0.1f;
    float k1a = (u - Ca) * it - Ca;
    float k1b = Ca - Cb * it;
    float xa = Ca + 0.5f * dlt * k1a, xb = Cb + 0.5f * dlt * k1b;
    float k2a = (u - xa) * it - xa;
    float k2b = xa - xb * it;
    xa = Ca + 0.5f * dlt * k2a; xb = Cb + 0.5f * dlt * k2b;
    float k3a = (u - xa) * it - xa;
    float k3b = xa - xb * it;
    xa = Ca + dlt * k3a; xb = Cb + dlt * k3b;
    float k4a = (u - xa) * it - xa;
    float k4b = xa - xb * it;
    Ca += (dlt / 6.0f) * (k1a + 2.0f * k2a + 2.0f * k3a + k4a);
    Cb += (dlt / 6.0f) * (k1b + 2.0f * k2b + 2.0f * k3b + k4b);
}

// ---------------- scan scratch (global; no dynamic alloc) ----------------
__device__ float g_v[NB * NCH * 2];   // zero-state chunk responses
__device__ float g_s[NB * NCH * 2];   // chunk start states

// pass1: chunk response from zero state (8-deep u prefetch for MLP)
__global__ void scan_p1(const float* __restrict__ inputs) {
    int idx = blockIdx.x * blockDim.x + threadIdx.x;
    if (idx >= NB * NCH) return;
    int b = idx >> 4, c = idx & 15;
    const float* up = inputs + ((size_t)b * NTT + c * CHUNK) * NF;
    float Ca = 0.f, Cb = 0.f;
    for (int t0 = 0; t0 < CHUNK; t0 += 8) {
        float uu[8];
        #pragma unroll
        for (int j = 0; j < 8; ++j) uu[j] = up[(size_t)(t0 + j) * NF];
        #pragma unroll
        for (int j = 0; j < 8; ++j) rk4_step(Ca, Cb, uu[j]);
    }
    g_v[idx * 2] = Ca; g_v[idx * 2 + 1] = Cb;
}

// pass2: per batch row, serial combine of NCH chunk boundaries.
// RK4 of this linear ODE is affine: s' = M s + n(u); chunk = M^64 s0 + v.
__global__ void scan_p2(const float* __restrict__ x0) {
    int b = blockIdx.x * blockDim.x + threadIdx.x;
    if (b >= NB) return;
    float m00 = 1.f, m10 = 0.f;               // M^64 columns via unit responses
    for (int t = 0; t < CHUNK; ++t) rk4_step(m00, m10, 0.f);
    float m01 = 0.f, m11 = 1.f;
    for (int t = 0; t < CHUNK; ++t) rk4_step(m01, m11, 0.f);
    float Ca = x0[2 * b], Cb = x0[2 * b + 1];
    #pragma unroll
    for (int c = 0; c < NCH; ++c) {
        int idx = b * NCH + c;
        g_s[idx * 2] = Ca; g_s[idx * 2 + 1] = Cb;
        float na = fmaf(m00, Ca, fmaf(m01, Cb, g_v[idx * 2]));
        float nb = fmaf(m10, Ca, fmaf(m11, Cb, g_v[idx * 2 + 1]));
        Ca = na; Cb = nb;
    }
}

// pass3: exact RK4 replay per chunk; writes PRE-update state into out.
__global__ void scan_p3(const float* __restrict__ inputs, float* __restrict__ out) {
    int idx = blockIdx.x * blockDim.x + threadIdx.x;
    if (idx >= NB * NCH) return;
    int b = idx >> 4, c = idx & 15;
    float Ca = g_s[idx * 2], Cb = g_s[idx * 2 + 1];
    const float* up = inputs + ((size_t)b * NTT + c * CHUNK) * NF;
    float2* op = (float2*)(out + ((size_t)b * NTT + c * CHUNK) * 2);
    for (int t0 = 0; t0 < CHUNK; t0 += 8) {
        float uu[8];
        #pragma unroll
        for (int j = 0; j < 8; ++j) uu[j] = up[(size_t)(t0 + j) * NF];
        #pragma unroll
        for (int j = 0; j < 8; ++j) {
            op[t0 + j] = make_float2(Ca, Cb);
            rk4_step(Ca, Cb, uu[j]);
        }
    }
}

// ============================================================================
// Persistent fused MLP, 512 threads / 16 warps.
// GEMM2 via mma.sync bf16 hi/lo 3-pass; warp w owns rows 32*(w&3), cols 32*(w>>2).
// ============================================================================
__global__ void __launch_bounds__(THREADS, 1)
mlp_kernel(const float* __restrict__ inputs,
           const float* __restrict__ W1,
           const float* __restrict__ b1,
           const float* __restrict__ W2,
           const float* __restrict__ b2,
           const float* __restrict__ W3,
           float* __restrict__ out) {
    extern __shared__ char smem[];
    const uint32_t smb = smem_u32(smem);
    const int tid  = threadIdx.x;
    const int wid  = tid >> 5;
    const int lane = tid & 31;

    // ---- one-time weight staging ----
    {
        for (int i = tid; i < 16384; i += THREADS) {
            int k = i >> 7, n = i & 127;
            float w = W2[i];                          // coalesced
            __nv_bfloat16 hb = __float2bfloat16(w);
            __nv_bfloat16 lb = __float2bfloat16(w - __bfloat162float(hb));
            uint32_t byte = (uint32_t)(n * MAT_STRIDE + k * 2);
            *(__nv_bfloat16*)(smem + OFF_BHI + byte) = hb;
            *(__nv_bfloat16*)(smem + OFF_BLO + byte) = lb;
        }
        float4* s1 = (float4*)(smem + OFF_W1);
        const float4* g1 = (const float4*)W1;
        for (int i = tid; i < 288; i += THREADS) s1[i] = g1[i];
        if (tid < 32)       ((float4*)(smem + OFF_B1))[tid]       = ((const float4*)b1)[tid];
        else if (tid < 64)  ((float4*)(smem + OFF_B2))[tid - 32]  = ((const float4*)b2)[tid - 32];
        else if (tid < 128) ((float4*)(smem + OFF_W3))[tid - 64]  = ((const float4*)W3)[tid - 64];
    }

    const int row = tid & 127;     // GEMM1 row
    const int jq  = tid >> 7;      // GEMM1 col quarter (32 cols each)
    const int mg  = wid & 3;       // MMA m-group -> rows 32*mg..+31
    const int ng  = wid >> 2;      // MMA n-group -> cols 32*ng..+31
    const int R0  = mg * 32;
    const int N0  = ng * 32;

    float*  xs  = (float*)(smem + OFF_XS);
    float*  b2s = (float*)(smem + OFF_B2);
    float*  W3s = (float*)(smem + OFF_W3);
    float2* red = (float2*)(smem + OFF_RED);   // [4][128]
    const float4* W1v = (const float4*)(smem + OFF_W1);
    const float4* b1v = (const float4*)(smem + OFF_B1);

    // ldmatrix per-lane address components
    const int a_row = ((lane >> 3) & 1) * 8 + (lane & 7);
    const int a_kh  = ((lane >> 4) & 1) * 16;
    const int b_row = ((lane >> 4) & 1) * 8 + (lane & 7);
    const int b_kh  = ((lane >> 3) & 1) * 16;

    for (int tile = blockIdx.x; tile < NTILES; tile += GRID_PERSIST) {
        __syncthreads();   // prior tile retired; also fences one-time staging

        // ---- stage X tile ----
        {
            const float* gx = inputs + (size_t)tile * TILE_ROWS * NF;
            #pragma unroll
            for (int i = 0; i < 3; ++i) {
                int idx = tid + THREADS * i;
                if (idx < TILE_ROWS * NF) xs[idx] = gx[idx];
            }
        }
        __syncthreads();

        // ---- GEMM1 + tanh + hi/lo split into padded A tiles ----
        {
            float x[9];
            #pragma unroll
            for (int k = 0; k < 9; ++k) x[k] = xs[row * NF + 1 + k];
            #pragma unroll
            for (int q = 0; q < 8; ++q) {
                const int j4 = jq * 8 + q;
                float4 a = b1v[j4];
                #pragma unroll
                for (int k = 0; k < 9; ++k) {
                    float4 w = W1v[k * 32 + j4];   // uniform within warp
                    a.x = fmaf(x[k], w.x, a.x);
                    a.y = fmaf(x[k], w.y, a.y);
                    a.z = fmaf(x[k], w.z, a.z);
                    a.w = fmaf(x[k], w.w, a.w);
                }
                float t0 = fast_tanh(a.x), t1 = fast_tanh(a.y);
                float t2 = fast_tanh(a.z), t3 = fast_tanh(a.w);
                __nv_bfloat16 h0 = __float2bfloat16(t0), h1 = __float2bfloat16(t1);
                __nv_bfloat16 h2 = __float2bfloat16(t2), h3 = __float2bfloat16(t3);
                __nv_bfloat16 l0 = __float2bfloat16(t0 - __bfloat162float(h0));
                __nv_bfloat16 l1 = __float2bfloat16(t1 - __bfloat162float(h1));
                __nv_bfloat16 l2 = __float2bfloat16(t2 - __bfloat162float(h2));
                __nv_bfloat16 l3 = __float2bfloat16(t3 - __bfloat162float(h3));
                uint2 hv, lv;
                hv.x = (uint32_t)__bfloat16_as_ushort(h0) | ((uint32_t)__bfloat16_as_ushort(h1) << 16);
                hv.y = (uint32_t)__bfloat16_as_ushort(h2) | ((uint32_t)__bfloat16_as_ushort(h3) << 16);
                lv.x = (uint32_t)__bfloat16_as_ushort(l0) | ((uint32_t)__bfloat16_as_ushort(l1) << 16);
                lv.y = (uint32_t)__bfloat16_as_ushort(l2) | ((uint32_t)__bfloat16_as_ushort(l3) << 16);
                const uint32_t byte = (uint32_t)(row * MAT_STRIDE + jq * 64 + q * 8);
                *(uint2*)(smem + OFF_AHI + byte) = hv;
                *(uint2*)(smem + OFF_ALO + byte) = lv;
            }
        }
        __syncthreads();

        // ---- GEMM2: mma.sync bf16 3-pass, 32x32 per warp ----
        float acc[2][4][4];
        #pragma unroll
        for (int mt = 0; mt < 2; ++mt)
            #pragma unroll
            for (int nt = 0; nt < 4; ++nt)
                #pragma unroll
                for (int c = 0; c < 4; ++c) acc[mt][nt][c] = 0.0f;

        #pragma unroll
        for (int ks = 0; ks < 8; ++ks) {
            const int K0 = ks * 32;
            uint32_t ahi[2][4], alo[2][4], bhi[4][2], blo[4][2];
            #pragma unroll
            for (int mt = 0; mt < 2; ++mt) {
                uint32_t addr = smb + (uint32_t)((R0 + mt * 16 + a_row) * MAT_STRIDE + K0 + a_kh);
                ldm_x4(ahi[mt], addr + OFF_AHI);
                ldm_x4(alo[mt], addr + OFF_ALO);
            }
            #pragma unroll
            for (int np = 0; np < 2; ++np) {
                uint32_t addr = smb + (uint32_t)((N0 + np * 16 + b_row) * MAT_STRIDE + K0 + b_kh);
                uint32_t r4[4];
                ldm_x4(r4, addr + OFF_BHI);
                bhi[2 * np][0] = r4[0]; bhi[2 * np][1] = r4[1];
                bhi[2 * np + 1][0] = r4[2]; bhi[2 * np + 1][1] = r4[3];
                ldm_x4(r4, addr + OFF_BLO);
                blo[2 * np][0] = r4[0]; blo[2 * np][1] = r4[1];
                blo[2 * np + 1][0] = r4[2]; blo[2 * np + 1][1] = r4[3];
            }
            #pragma unroll
            for (int mt = 0; mt < 2; ++mt)
                #pragma unroll
                for (int nt = 0; nt < 4; ++nt) {
                    mma_bf16(acc[mt][nt], ahi[mt], bhi[nt]);
                    mma_bf16(acc[mt][nt], ahi[mt], blo[nt]);
                    mma_bf16(acc[mt][nt], alo[mt], bhi[nt]);
                }
        }

        // ---- epilogue: tanh(acc + b2) @ W3 in registers, quad shfl reduce ----
        float rr[2][2][2];
        #pragma unroll
        for (int mt = 0; mt < 2; ++mt)
            #pragma unroll
            for (int hf = 0; hf < 2; ++hf) { rr[mt][hf][0] = 0.f; rr[mt][hf][1] = 0.f; }

        #pragma unroll
        for (int mt = 0; mt < 2; ++mt)
            #pragma unroll
            for (int nt = 0; nt < 4; ++nt) {
                const int c0 = N0 + nt * 8 + 2 * (lane & 3);
                const float w300 = W3s[2 * c0],     w301 = W3s[2 * c0 + 1];
                const float w310 = W3s[2 * c0 + 2], w311 = W3s[2 * c0 + 3];
                const float bb0 = b2s[c0], bb1 = b2s[c0 + 1];
                float h;
                h = fast_tanh(acc[mt][nt][0] + bb0);
                rr[mt][0][0] = fmaf(h, w300, rr[mt][0][0]);
                rr[mt][0][1] = fmaf(h, w301, rr[mt][0][1]);
                h = fast_tanh(acc[mt][nt][1] + bb1);
                rr[mt][0][0] = fmaf(h, w310, rr[mt][0][0]);
                rr[mt][0][1] = fmaf(h, w311, rr[mt][0][1]);
                h = fast_tanh(acc[mt][nt][2] + bb0);
                rr[mt][1][0] = fmaf(h, w300, rr[mt][1][0]);
                rr[mt][1][1] = fmaf(h, w301, rr[mt][1][1]);
                h = fast_tanh(acc[mt][nt][3] + bb1);
                rr[mt][1][0] = fmaf(h, w310, rr[mt][1][0]);
                rr[mt][1][1] = fmaf(h, w311, rr[mt][1][1]);
            }
        #pragma unroll
        for (int mt = 0; mt < 2; ++mt)
            #pragma unroll
            for (int hf = 0; hf < 2; ++hf)
                #pragma unroll
                for (int c = 0; c < 2; ++c) {
                    float v = rr[mt][hf][c];
                    v += __shfl_xor_sync(0xffffffffu, v, 1);
                    v += __shfl_xor_sync(0xffffffffu, v, 2);
                    rr[mt][hf][c] = v;
                }

        // stage each n-group's partials, then ng==0 combines and writes out
        if ((lane & 3) == 0) {
            #pragma unroll
            for (int mt = 0; mt < 2; ++mt)
                #pragma unroll
                for (int hf = 0; hf < 2; ++hf) {
                    const int r = R0 + mt * 16 + hf * 8 + (lane >> 2);
                    red[ng * 128 + r] = make_float2(rr[mt][hf][0], rr[mt][hf][1]);
                }
        }
        __syncthreads();
        if (ng == 0 && (lane & 3) == 0) {
            #pragma unroll
            for (int mt = 0; mt < 2; ++mt)
                #pragma unroll
                for (int hf = 0; hf < 2; ++hf) {
                    const int r = R0 + mt * 16 + hf * 8 + (lane >> 2);
                    const float2 p1 = red[128 + r];
                    const float2 p2 = red[256 + r];
                    const float2 p3 = red[384 + r];
                    const size_t o = ((size_t)tile * TILE_ROWS + r) * 2;
                    float2 v = *(float2*)(out + o);     // xG from scan
                    v.x += rr[mt][hf][0] + p1.x + p2.x + p3.x;
                    v.y += rr[mt][hf][1] + p1.y + p2.y + p3.y;
                    *(float2*)(out + o) = v;
                }
        }
    }
}

// ============================================================================
extern "C" void kernel_launch(void* const* d_in, const int* in_sizes, int n_in,
                              void* d_out, int out_size) {
    const float* inputs = (const float*)d_in[0];
    const float* x0     = (const float*)d_in[1];
    const float* W1     = (const float*)d_in[2];
    const float* b1     = (const float*)d_in[3];
    const float* W2     = (const float*)d_in[4];
    const float* b2     = (const float*)d_in[5];
    const float* W3     = (const float*)d_in[6];
    float* out = (float*)d_out;

    cudaFuncSetAttribute(mlp_kernel,
                         cudaFuncAttributeMaxDynamicSharedMemorySize, SMEM_BYTES);

    scan_p1<<<(NB * NCH) / 256, 256>>>(inputs);
    scan_p2<<<NB / 256, 256>>>(x0);
    scan_p3<<<(NB * NCH) / 256, 256>>>(inputs, out);
    mlp_kernel<<<GRID_PERSIST, THREADS, SMEM_BYTES>>>(inputs, W1, b1, W2, b2, W3, out);
}

// round 7
// speedup vs baseline: 2.9232x; 1.3747x over previous
#include <cuda_runtime.h>
#include <cuda_bf16.h>
#include <cstdint>

// ---------------- problem constants ----------------
#define NB   2048
#define NTT  1024
#define NF   10
#define NROWS (NB * NTT)
#define TILE_ROWS 128
#define NTILES (NROWS / TILE_ROWS)   // 16384
#define GRID_PERSIST 148
#define THREADS 512

// scan chunking
#define CHUNK 64
#define NCH (NTT / CHUNK)            // 16

// ---------------- smem layout (bytes) ----------------
#define MAT_STRIDE 272               // 128 bf16 cols padded to 17*16B -> LDSM conflict-free
#define MAT_BYTES  (128 * MAT_STRIDE)

#define OFF_W1   0                        // 1152 floats = 4608 B
#define OFF_B1   4608
#define OFF_B2   5120
#define OFF_W3   5632                     // 256 floats = 1024 B
#define OFF_A    6656                     // [2 bufs][hi,lo] x MAT_BYTES
#define OFF_BHI  (OFF_A + 4 * MAT_BYTES)  // 145920
#define OFF_BLO  (OFF_BHI + MAT_BYTES)    // 180736
#define SMEM_BYTES (OFF_BLO + MAT_BYTES)  // 215552

// named barriers: FULL = 1 + (j&1), EMPTY = 3 + (j&1)
__device__ __forceinline__ void bar_sync_named(int id) {
    asm volatile("bar.sync %0, %1;" :: "r"(id), "r"(THREADS) : "memory");
}
__device__ __forceinline__ void bar_arrive_named(int id) {
    asm volatile("bar.arrive %0, %1;" :: "r"(id), "r"(THREADS) : "memory");
}

// ---------------- PTX helpers ----------------
__device__ __forceinline__ uint32_t smem_u32(const void* p) {
    uint32_t a;
    asm("{ .reg .u64 t; cvta.to.shared.u64 t, %1; cvt.u32.u64 %0, t; }" : "=r"(a) : "l"(p));
    return a;
}
__device__ __forceinline__ void ldm_x4(uint32_t* r, uint32_t addr) {
    asm volatile("ldmatrix.sync.aligned.m8n8.x4.shared.b16 {%0,%1,%2,%3}, [%4];"
                 : "=r"(r[0]), "=r"(r[1]), "=r"(r[2]), "=r"(r[3]) : "r"(addr));
}
__device__ __forceinline__ void mma_bf16(float* d, const uint32_t* a, const uint32_t* b) {
    asm volatile(
        "mma.sync.aligned.m16n8k16.row.col.f32.bf16.bf16.f32 "
        "{%0,%1,%2,%3}, {%4,%5,%6,%7}, {%8,%9}, {%0,%1,%2,%3};"
        : "+f"(d[0]), "+f"(d[1]), "+f"(d[2]), "+f"(d[3])
        : "r"(a[0]), "r"(a[1]), "r"(a[2]), "r"(a[3]), "r"(b[0]), "r"(b[1]));
}

// ---------------- math helpers ----------------
__device__ __forceinline__ float fast_tanh(float x) {
    float e = __expf(2.0f * x);
    return 1.0f - __fdividef(2.0f, e + 1.0f);
}
// exact RK4 step, same arithmetic as reference
__device__ __forceinline__ void rk4_step(float& Ca, float& Cb, float u) {
    const float it = 0.1f, dlt = 0.1f;
    float k1a = (u - Ca) * it - Ca;
    float k1b = Ca - Cb * it;
    float xa = Ca + 0.5f * dlt * k1a, xb = Cb + 0.5f * dlt * k1b;
    float k2a = (u - xa) * it - xa;
    float k2b = xa - xb * it;
    xa = Ca + 0.5f * dlt * k2a; xb = Cb + 0.5f * dlt * k2b;
    float k3a = (u - xa) * it - xa;
    float k3b = xa - xb * it;
    xa = Ca + dlt * k3a; xb = Cb + dlt * k3b;
    float k4a = (u - xa) * it - xa;
    float k4b = xa - xb * it;
    Ca += (dlt / 6.0f) * (k1a + 2.0f * k2a + 2.0f * k3a + k4a);
    Cb += (dlt / 6.0f) * (k1b + 2.0f * k2b + 2.0f * k3b + k4b);
}

// ---------------- scan scratch ----------------
__device__ float g_v[NB * NCH * 2];
__device__ float g_s[NB * NCH * 2];

__global__ void scan_p1(const float* __restrict__ inputs) {
    int idx = blockIdx.x * blockDim.x + threadIdx.x;
    if (idx >= NB * NCH) return;
    int b = idx >> 4, c = idx & 15;
    const float* up = inputs + ((size_t)b * NTT + c * CHUNK) * NF;
    float Ca = 0.f, Cb = 0.f;
    for (int t0 = 0; t0 < CHUNK; t0 += 8) {
        float uu[8];
        #pragma unroll
        for (int j = 0; j < 8; ++j) uu[j] = up[(size_t)(t0 + j) * NF];
        #pragma unroll
        for (int j = 0; j < 8; ++j) rk4_step(Ca, Cb, uu[j]);
    }
    g_v[idx * 2] = Ca; g_v[idx * 2 + 1] = Cb;
}

__global__ void scan_p2(const float* __restrict__ x0) {
    int b = blockIdx.x * blockDim.x + threadIdx.x;
    if (b >= NB) return;
    float m00 = 1.f, m10 = 0.f;
    for (int t = 0; t < CHUNK; ++t) rk4_step(m00, m10, 0.f);
    float m01 = 0.f, m11 = 1.f;
    for (int t = 0; t < CHUNK; ++t) rk4_step(m01, m11, 0.f);
    float Ca = x0[2 * b], Cb = x0[2 * b + 1];
    #pragma unroll
    for (int c = 0; c < NCH; ++c) {
        int idx = b * NCH + c;
        g_s[idx * 2] = Ca; g_s[idx * 2 + 1] = Cb;
        float na = fmaf(m00, Ca, fmaf(m01, Cb, g_v[idx * 2]));
        float nb = fmaf(m10, Ca, fmaf(m11, Cb, g_v[idx * 2 + 1]));
        Ca = na; Cb = nb;
    }
}

__global__ void scan_p3(const float* __restrict__ inputs, float* __restrict__ out) {
    int idx = blockIdx.x * blockDim.x + threadIdx.x;
    if (idx >= NB * NCH) return;
    int b = idx >> 4, c = idx & 15;
    float Ca = g_s[idx * 2], Cb = g_s[idx * 2 + 1];
    const float* up = inputs + ((size_t)b * NTT + c * CHUNK) * NF;
    float2* op = (float2*)(out + ((size_t)b * NTT + c * CHUNK) * 2);
    for (int t0 = 0; t0 < CHUNK; t0 += 8) {
        float uu[8];
        #pragma unroll
        for (int j = 0; j < 8; ++j) uu[j] = up[(size_t)(t0 + j) * NF];
        #pragma unroll
        for (int j = 0; j < 8; ++j) {
            op[t0 + j] = make_float2(Ca, Cb);
            rk4_step(Ca, Cb, uu[j]);
        }
    }
}

// ============================================================================
// Persistent fused MLP with producer/consumer warp specialization.
// Warps 8-15: GEMM1+tanh+hi/lo split into double-buffered A tiles.
// Warps 0-7:  ldmatrix + 3-pass bf16 mma.sync + tanh/W3 epilogue + store.
// Handshake: named barriers (FULL 1/2, EMPTY 3/4), pipeline depth 2.
// ============================================================================
__global__ void __launch_bounds__(THREADS, 1)
mlp_kernel(const float* __restrict__ inputs,
           const float* __restrict__ W1,
           const float* __restrict__ b1,
           const float* __restrict__ W2,
           const float* __restrict__ b2,
           const float* __restrict__ W3,
           float* __restrict__ out) {
    extern __shared__ char smem[];
    const uint32_t smb = smem_u32(smem);
    const int tid  = threadIdx.x;
    const int wid  = tid >> 5;
    const int lane = tid & 31;

    // ---- one-time weight staging (all 512 threads) ----
    {
        for (int i = tid; i < 16384; i += THREADS) {
            int k = i >> 7, n = i & 127;
            float w = W2[i];                           // coalesced
            __nv_bfloat16 hb = __float2bfloat16(w);
            __nv_bfloat16 lb = __float2bfloat16(w - __bfloat162float(hb));
            uint32_t byte = (uint32_t)(n * MAT_STRIDE + k * 2);
            *(__nv_bfloat16*)(smem + OFF_BHI + byte) = hb;
            *(__nv_bfloat16*)(smem + OFF_BLO + byte) = lb;
        }
        float4* s1 = (float4*)(smem + OFF_W1);
        const float4* g1 = (const float4*)W1;
        for (int i = tid; i < 288; i += THREADS) s1[i] = g1[i];
        if (tid < 32)       ((float4*)(smem + OFF_B1))[tid]       = ((const float4*)b1)[tid];
        else if (tid < 64)  ((float4*)(smem + OFF_B2))[tid - 32]  = ((const float4*)b2)[tid - 32];
        else if (tid < 128) ((float4*)(smem + OFF_W3))[tid - 64]  = ((const float4*)W3)[tid - 64];
    }
    __syncthreads();

    if (wid >= 8) {
        // ==================== PRODUCER ====================
        const int ptid = tid - 256;
        const int row  = ptid & 127;    // tile row
        const int jh   = ptid >> 7;     // col half (64 cols)
        const float4* W1v = (const float4*)(smem + OFF_W1);
        const float4* b1v = (const float4*)(smem + OFF_B1);

        int j = 0;
        for (int tile = blockIdx.x; tile < NTILES; tile += GRID_PERSIST, ++j) {
            if (j >= 2) bar_sync_named(3 + (j & 1));   // wait buffer free

            // direct LDG of this row's 9 features (8B-aligned float2s)
            const float* xr = inputs + ((size_t)tile * TILE_ROWS + row) * NF;
            float2 p0 = *(const float2*)(xr);
            float2 p1 = *(const float2*)(xr + 2);
            float2 p2 = *(const float2*)(xr + 4);
            float2 p3 = *(const float2*)(xr + 6);
            float2 p4 = *(const float2*)(xr + 8);
            float x[9] = {p0.y, p1.x, p1.y, p2.x, p2.y, p3.x, p3.y, p4.x, p4.y};

            char* abhi = smem + OFF_A + (j & 1) * (2 * MAT_BYTES);
            char* ablo = abhi + MAT_BYTES;

            #pragma unroll
            for (int q = 0; q < 16; ++q) {
                const int j4 = jh * 16 + q;
                float4 a = b1v[j4];
                #pragma unroll
                for (int k = 0; k < 9; ++k) {
                    float4 w = W1v[k * 32 + j4];       // uniform within warp
                    a.x = fmaf(x[k], w.x, a.x);
                    a.y = fmaf(x[k], w.y, a.y);
                    a.z = fmaf(x[k], w.z, a.z);
                    a.w = fmaf(x[k], w.w, a.w);
                }
                float t0 = fast_tanh(a.x), t1 = fast_tanh(a.y);
                float t2 = fast_tanh(a.z), t3 = fast_tanh(a.w);
                __nv_bfloat16 h0 = __float2bfloat16(t0), h1 = __float2bfloat16(t1);
                __nv_bfloat16 h2 = __float2bfloat16(t2), h3 = __float2bfloat16(t3);
                __nv_bfloat16 l0 = __float2bfloat16(t0 - __bfloat162float(h0));
                __nv_bfloat16 l1 = __float2bfloat16(t1 - __bfloat162float(h1));
                __nv_bfloat16 l2 = __float2bfloat16(t2 - __bfloat162float(h2));
                __nv_bfloat16 l3 = __float2bfloat16(t3 - __bfloat162float(h3));
                uint2 hv, lv;
                hv.x = (uint32_t)__bfloat16_as_ushort(h0) | ((uint32_t)__bfloat16_as_ushort(h1) << 16);
                hv.y = (uint32_t)__bfloat16_as_ushort(h2) | ((uint32_t)__bfloat16_as_ushort(h3) << 16);
                lv.x = (uint32_t)__bfloat16_as_ushort(l0) | ((uint32_t)__bfloat16_as_ushort(l1) << 16);
                lv.y = (uint32_t)__bfloat16_as_ushort(l2) | ((uint32_t)__bfloat16_as_ushort(l3) << 16);
                const uint32_t byte = (uint32_t)(row * MAT_STRIDE + jh * 128 + q * 8);
                *(uint2*)(abhi + byte) = hv;
                *(uint2*)(ablo + byte) = lv;
            }
            bar_arrive_named(1 + (j & 1));             // publish buffer
        }
    } else {
        // ==================== CONSUMER ====================
        const int R0 = wid * 16;                       // 16 rows per warp
        const int aRow = lane & 15;
        const int aKh  = (lane >> 4) * 16;
        const int bRow = ((lane >> 4) & 1) * 8 + (lane & 7);
        const int bKh  = ((lane >> 3) & 1) * 16;
        const float* b2s = (const float*)(smem + OFF_B2);
        const float* W3s = (const float*)(smem + OFF_W3);

        int j = 0;
        for (int tile = blockIdx.x; tile < NTILES; tile += GRID_PERSIST, ++j) {
            bar_sync_named(1 + (j & 1));               // wait buffer full
            const uint32_t ahiB = smb + OFF_A + (uint32_t)((j & 1) * (2 * MAT_BYTES));
            const uint32_t aloB = ahiB + MAT_BYTES;

            float acc[16][4];
            #pragma unroll
            for (int nt = 0; nt < 16; ++nt)
                #pragma unroll
                for (int c = 0; c < 4; ++c) acc[nt][c] = 0.0f;

            #pragma unroll
            for (int ks = 0; ks < 8; ++ks) {
                const int K0 = ks * 32;
                const uint32_t aoff = (uint32_t)((R0 + aRow) * MAT_STRIDE + K0 + aKh);
                uint32_t ahi[4], alo[4];
                ldm_x4(ahi, ahiB + aoff);
                ldm_x4(alo, aloB + aoff);
                #pragma unroll
                for (int h = 0; h < 2; ++h) {
                    uint32_t bh[8][2], bl[8][2];
                    #pragma unroll
                    for (int np = 0; np < 4; ++np) {
                        const uint32_t boff =
                            (uint32_t)((h * 64 + np * 16 + bRow) * MAT_STRIDE + K0 + bKh);
                        uint32_t r4[4];
                        ldm_x4(r4, smb + OFF_BHI + boff);
                        bh[2 * np][0] = r4[0]; bh[2 * np][1] = r4[1];
                        bh[2 * np + 1][0] = r4[2]; bh[2 * np + 1][1] = r4[3];
                        ldm_x4(r4, smb + OFF_BLO + boff);
                        bl[2 * np][0] = r4[0]; bl[2 * np][1] = r4[1];
                        bl[2 * np + 1][0] = r4[2]; bl[2 * np + 1][1] = r4[3];
                    }
                    #pragma unroll
                    for (int nt = 0; nt < 8; ++nt) {
                        float* d = acc[h * 8 + nt];
                        mma_bf16(d, ahi, bh[nt]);
                        mma_bf16(d, ahi, bl[nt]);
                        mma_bf16(d, alo, bh[nt]);
                    }
                }
            }
            bar_arrive_named(3 + (j & 1));             // buffer free (A reads done)

            // ---- epilogue: tanh(acc + b2) @ W3, warp-local ----
            float rr[2][2];
            rr[0][0] = rr[0][1] = rr[1][0] = rr[1][1] = 0.f;
            #pragma unroll
            for (int nt = 0; nt < 16; ++nt) {
                const int c0 = nt * 8 + 2 * (lane & 3);
                const float w300 = W3s[2 * c0],     w301 = W3s[2 * c0 + 1];
                const float w310 = W3s[2 * c0 + 2], w311 = W3s[2 * c0 + 3];
                const float bb0 = b2s[c0], bb1 = b2s[c0 + 1];
                float h;
                h = fast_tanh(acc[nt][0] + bb0);
                rr[0][0] = fmaf(h, w300, rr[0][0]);
                rr[0][1] = fmaf(h, w301, rr[0][1]);
                h = fast_tanh(acc[nt][1] + bb1);
                rr[0][0] = fmaf(h, w310, rr[0][0]);
                rr[0][1] = fmaf(h, w311, rr[0][1]);
                h = fast_tanh(acc[nt][2] + bb0);
                rr[1][0] = fmaf(h, w300, rr[1][0]);
                rr[1][1] = fmaf(h, w301, rr[1][1]);
                h = fast_tanh(acc[nt][3] + bb1);
                rr[1][0] = fmaf(h, w310, rr[1][0]);
                rr[1][1] = fmaf(h, w311, rr[1][1]);
            }
            #pragma unroll
            for (int hf = 0; hf < 2; ++hf)
                #pragma unroll
                for (int c = 0; c < 2; ++c) {
                    float v = rr[hf][c];
                    v += __shfl_xor_sync(0xffffffffu, v, 1);
                    v += __shfl_xor_sync(0xffffffffu, v, 2);
                    rr[hf][c] = v;
                }
            if ((lane & 3) == 0) {
                #pragma unroll
                for (int hf = 0; hf < 2; ++hf) {
                    const int r = R0 + hf * 8 + (lane >> 2);
                    const size_t o = ((size_t)tile * TILE_ROWS + r) * 2;
                    float2 v = *(float2*)(out + o);    // xG from scan
                    v.x += rr[hf][0];
                    v.y += rr[hf][1];
                    *(float2*)(out + o) = v;
                }
            }
        }
    }
}

// ============================================================================
extern "C" void kernel_launch(void* const* d_in, const int* in_sizes, int n_in,
                              void* d_out, int out_size) {
    const float* inputs = (const float*)d_in[0];
    const float* x0     = (const float*)d_in[1];
    const float* W1     = (const float*)d_in[2];
    const float* b1     = (const float*)d_in[3];
    const float* W2     = (const float*)d_in[4];
    const float* b2     = (const float*)d_in[5];
    const float* W3     = (const float*)d_in[6];
    float* out = (float*)d_out;

    cudaFuncSetAttribute(mlp_kernel,
                         cudaFuncAttributeMaxDynamicSharedMemorySize, SMEM_BYTES);

    scan_p1<<<(NB * NCH) / 256, 256>>>(inputs);
    scan_p2<<<NB / 256, 256>>>(x0);
    scan_p3<<<(NB * NCH) / 256, 256>>>(inputs, out);
    mlp_kernel<<<GRID_PERSIST, THREADS, SMEM_BYTES>>>(inputs, W1, b1, W2, b2, W3, out);
}